// round 16
// baseline (speedup 1.0000x reference)
#include <cuda_runtime.h>
#include <math.h>

// N = 100000 nodes, E = 3200000 edges.
// g_packed[i] = {copysign(l_i, qw_i), qx, qy, qz} (16B fp32 node record).
// g_acc: 32B/node: [2i]={sumQ0..3} (v4 RED), [2i+1].xy={Z,sumL} (v2 RED).
// Prep is FUSED into the edge kernel: blocks bid<nprep prep their node chunk,
// publish via threadfence+atomicAdd(g_prep_done); all blocks prefetch their
// coalesced edge streams, then acquire-spin until prep is globally done.
// Deadlock-free: launch_bounds(256,4) => wave-1 >= 592 blocks >= nprep=391,
// and prep blocks depend on nothing. final_kernel resets g_prep_done.
#define MAXN 131072
__device__ float4 g_packed[MAXN];
__device__ float4 g_acc[MAXN * 2];
__device__ unsigned int g_prep_done;   // zero-init; reset by final_kernel

#define TEMP 10.0f

__device__ __forceinline__ unsigned int ld_acquire_gpu(unsigned int* p) {
    unsigned int v;
    asm volatile("ld.global.acquire.gpu.u32 %0, [%1];" : "=r"(v) : "l"(p)
                 : "memory");
    return v;
}

// ---------------------------------------------------------------------------
// Per-edge body: ONE random 16B gather + v4 RED + v2 RED (same 32B record).
// Logits bounded in [0,10) -> stable-softmax max subtraction cancels, omitted.
// ---------------------------------------------------------------------------
__device__ __forceinline__ void edge_body(int s, int d, float4 a, float w) {
    float4 p = __ldg(&g_packed[s]);
    float l  = fabsf(p.x);
    float bx = p.y, by = p.z, bz = p.w;
    float t  = 1.0f - (bx * bx + by * by + bz * bz);
    float bw = copysignf(sqrtf(fmaxf(t, 0.0f)), p.x);

    float aw = a.x, ax = a.y, ay = a.z, az = a.w;
    float cw = aw * bw - ax * bx - ay * by - az * bz;
    float cx = aw * bx + ax * bw + ay * bz - az * by;
    float cy = aw * by - ax * bz + ay * bw + az * bx;
    float cz = aw * bz + ax * by - ay * bx + az * bw;

    float ex = __expf(TEMP * w * l);

    float* acc = (float*)&g_acc[2 * d];
    asm volatile("red.global.add.v4.f32 [%0], {%1, %2, %3, %4};"
                 :: "l"(acc), "f"(ex * cw), "f"(ex * cx),
                    "f"(ex * cy), "f"(ex * cz)
                 : "memory");
    asm volatile("red.global.add.v2.f32 [%0], {%1, %2};"
                 :: "l"(acc + 4), "f"(ex), "f"(ex * l)
                 : "memory");
}

// ---------------------------------------------------------------------------
// Fused prep + edge kernel.
// ---------------------------------------------------------------------------
__global__ void __launch_bounds__(256, 4) edge_kernel(
    const float* __restrict__ node_levels,
    const float4* __restrict__ node_q,
    const float4* __restrict__ edge_rel_q,
    const float* __restrict__ edge_w,
    const int* __restrict__ src,
    const int* __restrict__ dst,
    int N, int E, int nprep_blocks) {
    int bid = blockIdx.x;
    int tid = threadIdx.x;

    // --- Phase 1: prep (blocks [0, nprep_blocks) only) ---
    if (bid < nprep_blocks) {
        int i = bid * 256 + tid;
        if (i < N) {
            float l  = __ldg(&node_levels[i]);
            float4 q = __ldg(&node_q[i]);          // (w,x,y,z)
            float es = __expf(TEMP * l);
            g_acc[2 * i]     = make_float4(es * q.x, es * q.y,
                                           es * q.z, es * q.w);
            g_acc[2 * i + 1] = make_float4(es, es * l, 0.f, 0.f);
            g_packed[i] = make_float4(copysignf(l, q.x), q.y, q.z, q.w);
        }
        __syncthreads();
        __threadfence();                           // release our prep stores
        if (tid == 0) atomicAdd(&g_prep_done, 1u);
    }

    // --- Phase 2: prefetch coalesced edge streams (independent of prep) ---
    int t = bid * 256 + tid;
    int e = 2 * t;
    bool pair = (e + 1 < E);
    bool solo = (!pair) && (e < E);
    int2 s2, d2; float2 w2; float4 a0, a1;
    if (pair) {
        s2 = __ldg(&((const int2*)src)[t]);
        d2 = __ldg(&((const int2*)dst)[t]);
        w2 = __ldg(&((const float2*)edge_w)[t]);
        asm("ld.global.nc.v8.f32 {%0,%1,%2,%3,%4,%5,%6,%7}, [%8];"
            : "=f"(a0.x), "=f"(a0.y), "=f"(a0.z), "=f"(a0.w),
              "=f"(a1.x), "=f"(a1.y), "=f"(a1.z), "=f"(a1.w)
            : "l"(edge_rel_q + e));
    } else if (solo) {
        s2.x = __ldg(&src[e]); d2.x = __ldg(&dst[e]);
        w2.x = __ldg(&edge_w[e]); a0 = __ldg(&edge_rel_q[e]);
    }

    // --- Phase 3: wait for ALL prep blocks (acquire), then scatter ---
    if (tid == 0) {
        while (ld_acquire_gpu(&g_prep_done) < (unsigned int)nprep_blocks)
            __nanosleep(64);
        __threadfence();
    }
    __syncthreads();

    if (pair) {
        edge_body(s2.x, d2.x, a0, w2.x);
        edge_body(s2.y, d2.y, a1, w2.y);
    } else if (solo) {
        edge_body(s2.x, d2.x, a0, w2.x);
    }
}

// ---------------------------------------------------------------------------
// Finalize: read-only on accumulators (self term already inside).
//   out_q = normalize(sum_q)   (Z cancels);  out_levels = sumL / Z
// Also resets g_prep_done for the next graph replay.
// Output layout: out[0..4N) = out_q row-major, out[4N..5N) = out_levels.
// ---------------------------------------------------------------------------
__global__ void __launch_bounds__(256) final_kernel(float* __restrict__ out,
                                                    int N) {
    int i = blockIdx.x * blockDim.x + threadIdx.x;
    if (i == 0) g_prep_done = 0u;   // replay-safe reset (stream-ordered)
    if (i >= N) return;

    float4 acc = g_acc[2 * i];
    float4 zl  = g_acc[2 * i + 1];

    float n2 = acc.x * acc.x + acc.y * acc.y + acc.z * acc.z + acc.w * acc.w;
    float inv = rsqrtf(fmaxf(n2, 1e-24f));
    ((float4*)out)[i] = make_float4(acc.x * inv, acc.y * inv,
                                    acc.z * inv, acc.w * inv);
    out[4 * N + i] = __fdividef(zl.y, zl.x);
}

extern "C" void kernel_launch(void* const* d_in, const int* in_sizes, int n_in,
                              void* d_out, int out_size) {
    const float*  node_levels = (const float*)d_in[0];
    const float4* node_q      = (const float4*)d_in[1];
    const float4* edge_rel_q  = (const float4*)d_in[2];
    const float*  edge_w      = (const float*)d_in[3];
    const int*    src         = (const int*)d_in[4];
    const int*    dst         = (const int*)d_in[5];

    int N = in_sizes[0];
    int E = in_sizes[3];

    float* out = (float*)d_out;

    const int T = 256;
    int nprep_blocks = (N + T - 1) / T;                 // 391
    int edge_threads = (E + 1) / 2;
    int edge_blocks  = (edge_threads + T - 1) / T;      // 6250 (>= nprep)

    edge_kernel<<<edge_blocks, T>>>(node_levels, node_q, edge_rel_q, edge_w,
                                    src, dst, N, E, nprep_blocks);
    final_kernel<<<(N + T - 1) / T, T>>>(out, N);
}

// round 17
// speedup vs baseline: 1.5803x; 1.5803x over previous
#include <cuda_runtime.h>
#include <math.h>

// N = 100000 nodes, E = 3200000 edges.
// g_packed[i] = {copysign(l_i, qw_i), qx, qy, qz} (16B fp32 node record; l>=0
//   so its sign bit carries qw's sign; qw rebuilt from unit-norm invariant).
// g_q[i] = {sumQ0..3}, g_zl[i] = {Z, sumL}: initialized by prep with the exact
//   self term (overwrite semantics -> graph-replay robust), accumulated by
//   edge REDs, read-only in finalize.
// Schedule: three plain launches (PDL / fused-barrier variants all measured
// slower or neutral). Edge kernel is at the 3-random-op/edge LSU floor.
#define MAXN 131072
__device__ float4 g_packed[MAXN];
__device__ float4 g_q[MAXN];
__device__ float2 g_zl[MAXN];

#define TEMP 10.0f

// ---------------------------------------------------------------------------
// Prep: 1 node/thread, T=128 for finer wave balance on this small grid.
// node_q rows are (w,x,y,z).
// ---------------------------------------------------------------------------
__global__ void __launch_bounds__(128) prep_kernel(
    const float* __restrict__ node_levels,
    const float4* __restrict__ node_q,
    int N) {
    int i = blockIdx.x * blockDim.x + threadIdx.x;
    if (i >= N) return;
    float l  = __ldg(&node_levels[i]);
    float4 q = __ldg(&node_q[i]);
    float es = __expf(TEMP * l);

    g_q[i]  = make_float4(es * q.x, es * q.y, es * q.z, es * q.w);
    g_zl[i] = make_float2(es, es * l);
    g_packed[i] = make_float4(copysignf(l, q.x), q.y, q.z, q.w);
}

// ---------------------------------------------------------------------------
// Edge scatter, 2 edges per thread (proven optimal form).
// Per edge: ONE random 16B gather + v4 RED + v2 RED.
// Logits bounded in [0,10) -> stable-softmax max subtraction cancels, omitted.
// ---------------------------------------------------------------------------
__device__ __forceinline__ void edge_body(int s, int d, float4 a, float w) {
    float4 p = __ldg(&g_packed[s]);
    float l  = fabsf(p.x);
    float bx = p.y, by = p.z, bz = p.w;
    float t  = 1.0f - (bx * bx + by * by + bz * bz);
    float bw = copysignf(sqrtf(fmaxf(t, 0.0f)), p.x);

    float aw = a.x, ax = a.y, ay = a.z, az = a.w;
    float cw = aw * bw - ax * bx - ay * by - az * bz;
    float cx = aw * bx + ax * bw + ay * bz - az * by;
    float cy = aw * by - ax * bz + ay * bw + az * bx;
    float cz = aw * bz + ax * by - ay * bx + az * bw;

    float ex = __expf(TEMP * w * l);

    asm volatile("red.global.add.v4.f32 [%0], {%1, %2, %3, %4};"
                 :: "l"(&g_q[d]), "f"(ex * cw), "f"(ex * cx),
                    "f"(ex * cy), "f"(ex * cz)
                 : "memory");
    asm volatile("red.global.add.v2.f32 [%0], {%1, %2};"
                 :: "l"(&g_zl[d]), "f"(ex), "f"(ex * l)
                 : "memory");
}

__global__ void __launch_bounds__(256) edge_kernel(
    const float4* __restrict__ edge_rel_q,
    const float* __restrict__ edge_w,
    const int* __restrict__ src,
    const int* __restrict__ dst,
    int E) {
    int t = blockIdx.x * blockDim.x + threadIdx.x;
    int e = 2 * t;
    if (e >= E) return;

    if (e + 1 < E) {
        int2   s2 = __ldg(&((const int2*)src)[t]);
        int2   d2 = __ldg(&((const int2*)dst)[t]);
        float2 w2 = __ldg(&((const float2*)edge_w)[t]);
        float4 a0, a1;   // 256-bit stream load (neutral perf, fewer instrs)
        asm("ld.global.nc.v8.f32 {%0,%1,%2,%3,%4,%5,%6,%7}, [%8];"
            : "=f"(a0.x), "=f"(a0.y), "=f"(a0.z), "=f"(a0.w),
              "=f"(a1.x), "=f"(a1.y), "=f"(a1.z), "=f"(a1.w)
            : "l"(edge_rel_q + e));
        edge_body(s2.x, d2.x, a0, w2.x);
        edge_body(s2.y, d2.y, a1, w2.y);
    } else {
        edge_body(__ldg(&src[e]), __ldg(&dst[e]), __ldg(&edge_rel_q[e]),
                  __ldg(&edge_w[e]));
    }
}

// ---------------------------------------------------------------------------
// Finalize: read-only on accumulators (self term already inside). T=128.
//   out_q = normalize(sum_q)            (Z cancels inside normalize)
//   out_levels = sumL / Z
// Output layout: out[0..4N) = out_q row-major, out[4N..5N) = out_levels.
// ---------------------------------------------------------------------------
__global__ void __launch_bounds__(128) final_kernel(float* __restrict__ out,
                                                    int N) {
    int i = blockIdx.x * blockDim.x + threadIdx.x;
    if (i >= N) return;

    float4 acc = g_q[i];
    float2 zl  = g_zl[i];

    float n2 = acc.x * acc.x + acc.y * acc.y + acc.z * acc.z + acc.w * acc.w;
    float inv = rsqrtf(fmaxf(n2, 1e-24f));
    ((float4*)out)[i] = make_float4(acc.x * inv, acc.y * inv,
                                    acc.z * inv, acc.w * inv);
    out[4 * N + i] = __fdividef(zl.y, zl.x);
}

extern "C" void kernel_launch(void* const* d_in, const int* in_sizes, int n_in,
                              void* d_out, int out_size) {
    const float*  node_levels = (const float*)d_in[0];
    const float4* node_q      = (const float4*)d_in[1];
    const float4* edge_rel_q  = (const float4*)d_in[2];
    const float*  edge_w      = (const float*)d_in[3];
    const int*    src         = (const int*)d_in[4];
    const int*    dst         = (const int*)d_in[5];

    int N = in_sizes[0];
    int E = in_sizes[3];

    float* out = (float*)d_out;

    prep_kernel<<<(N + 127) / 128, 128>>>(node_levels, node_q, N);
    int edge_threads = (E + 1) / 2;
    edge_kernel<<<(edge_threads + 255) / 256, 256>>>(edge_rel_q, edge_w,
                                                     src, dst, E);
    final_kernel<<<(N + 127) / 128, 128>>>(out, N);
}